// round 5
// baseline (speedup 1.0000x reference)
#include <cuda_runtime.h>
#include <math.h>

// Problem dims (fixed by the dataset)
#define L_SEQ   4096
#define B_SZ    8
#define D_SZ    1024
#define N_HEADS 16
#define NHALF   8                  // heads per thread (16 split across 2 lanes)

// Chunked-scan config
#define NCHUNK  32
#define CHUNK   (L_SEQ / NCHUNK)   // 128
#define BD      (B_SZ * D_SZ)      // 8192
#define BDN     (B_SZ * D_SZ * N_HEADS)

// Scratch (no cudaMalloc allowed)
__device__ float g_q[D_SZ * N_HEADS];
__device__ float g_c[D_SZ * N_HEADS];
__device__ float g_state[NCHUNK * BDN];

// ---------------------------------------------------------------------------
// Phase 0: coefficients
//   p = sigmoid(damping); q = 1 - p*sigmoid(decay)  (q in (0,1))
//   c = p * ema * proj * (1/sqrt(N)) = p * ema * proj * 0.25
// ---------------------------------------------------------------------------
__global__ void coef_kernel(const float* __restrict__ damping,
                            const float* __restrict__ decay,
                            const float* __restrict__ ema,
                            const float* __restrict__ proj) {
    int i = blockIdx.x * blockDim.x + threadIdx.x;
    if (i >= D_SZ * N_HEADS) return;
    float p = 1.0f / (1.0f + expf(-damping[i]));
    float s = 1.0f / (1.0f + expf(-decay[i]));
    g_q[i] = 1.0f - p * s;
    g_c[i] = p * ema[i] * proj[i] * 0.25f;
}

// ---------------------------------------------------------------------------
// Phase 1: chunk-local scans, zero init; store final states.
// Head-split: thread = (d, half); each thread owns 8 of the 16 heads.
// block = 256 (128 d x 2 halves); grid (D/128, B, NCHUNK).
// Low register count -> high occupancy to hide the x-load latency.
// ---------------------------------------------------------------------------
__global__ void __launch_bounds__(256, 8) scan_local_kernel(const float* __restrict__ x) {
    const int t    = threadIdx.x;
    const int d    = blockIdx.x * 128 + (t >> 1);
    const int half = t & 1;
    const int b  = blockIdx.y;
    const int ck = blockIdx.z;

    float q[NHALF], h[NHALF];
    const float4* qv = (const float4*)(g_q + d * N_HEADS + half * NHALF);
#pragma unroll
    for (int j = 0; j < 2; j++) {
        float4 v = qv[j];
        q[4*j+0] = v.x; q[4*j+1] = v.y; q[4*j+2] = v.z; q[4*j+3] = v.w;
    }
#pragma unroll
    for (int n = 0; n < NHALF; n++) h[n] = 0.0f;

    const float* xp = x + (size_t)ck * CHUNK * BD + (size_t)b * D_SZ + d;

    for (int l0 = 0; l0 < CHUNK; l0 += 8) {
        float xv[8];
#pragma unroll
        for (int u = 0; u < 8; u++) xv[u] = xp[(size_t)(l0 + u) * BD];
#pragma unroll
        for (int u = 0; u < 8; u++) {
#pragma unroll
            for (int n = 0; n < NHALF; n++) h[n] = fmaf(q[n], h[n], xv[u]);
        }
    }

    float4* sp = (float4*)(g_state + ((size_t)(ck * B_SZ + b) * D_SZ + d) * N_HEADS
                           + half * NHALF);
#pragma unroll
    for (int j = 0; j < 2; j++)
        sp[j] = make_float4(h[4*j+0], h[4*j+1], h[4*j+2], h[4*j+3]);
}

// ---------------------------------------------------------------------------
// Phase 2: cross-chunk prefix (diagonal, decay factor q^CHUNK), in place.
//   g_state[c] becomes the INITIAL (exclusive) state of chunk c.
// ---------------------------------------------------------------------------
__global__ void prefix_kernel() {
    int i = blockIdx.x * blockDim.x + threadIdx.x;
    if (i >= BDN) return;
    float q = g_q[i % (D_SZ * N_HEADS)];
    float qc = q;                    // q^128 by 7 squarings (CHUNK = 128)
#pragma unroll
    for (int k = 0; k < 7; k++) qc *= qc;

    float H = 0.0f;
#pragma unroll
    for (int c = 0; c < NCHUNK; c++) {
        float* ptr = g_state + (size_t)c * BDN + i;
        float S = *ptr;
        *ptr = H;
        H = fmaf(qc, H, S);
    }
}

// ---------------------------------------------------------------------------
// Phase 3: full scan + projection + residual + relu, head-split.
// Each lane pair combines its half-projections with one shfl_xor(1).
// ---------------------------------------------------------------------------
__global__ void __launch_bounds__(256, 6) scan_out_kernel(const float* __restrict__ x,
                                                          const float* __restrict__ rw,
                                                          float* __restrict__ out) {
    const int t    = threadIdx.x;
    const int d    = blockIdx.x * 128 + (t >> 1);
    const int half = t & 1;
    const int b  = blockIdx.y;
    const int ck = blockIdx.z;

    float q[NHALF], c[NHALF], h[NHALF];
    const float4* qv = (const float4*)(g_q + d * N_HEADS + half * NHALF);
    const float4* cv = (const float4*)(g_c + d * N_HEADS + half * NHALF);
    const float4* sv = (const float4*)(g_state + ((size_t)(ck * B_SZ + b) * D_SZ + d) * N_HEADS
                                       + half * NHALF);
#pragma unroll
    for (int j = 0; j < 2; j++) {
        float4 vq = qv[j], vc = cv[j], vh = sv[j];
        q[4*j+0] = vq.x; q[4*j+1] = vq.y; q[4*j+2] = vq.z; q[4*j+3] = vq.w;
        c[4*j+0] = vc.x; c[4*j+1] = vc.y; c[4*j+2] = vc.z; c[4*j+3] = vc.w;
        h[4*j+0] = vh.x; h[4*j+1] = vh.y; h[4*j+2] = vh.z; h[4*j+3] = vh.w;
    }
    const float rw_d = rw[d];

    const size_t base = (size_t)ck * CHUNK * BD + (size_t)b * D_SZ + d;
    const float* xp = x + base;
    float*       op = out + base;

    for (int l0 = 0; l0 < CHUNK; l0 += 4) {
        float xv[4];
#pragma unroll
        for (int u = 0; u < 4; u++) xv[u] = xp[(size_t)(l0 + u) * BD];
#pragma unroll
        for (int u = 0; u < 4; u++) {
#pragma unroll
            for (int n = 0; n < NHALF; n++) h[n] = fmaf(q[n], h[n], xv[u]);
            // half-projection: two accumulator chains for ILP
            float s0 = 0.0f, s1 = 0.0f;
#pragma unroll
            for (int n = 0; n < NHALF; n += 2) {
                s0 = fmaf(c[n + 0], h[n + 0], s0);
                s1 = fmaf(c[n + 1], h[n + 1], s1);
            }
            float s = s0 + s1;
            // combine the two head-halves across the lane pair
            s += __shfl_xor_sync(0xffffffffu, s, 1);
            if (half == 0) {
                float val = fmaf(xv[u], rw_d, s);
                op[(size_t)(l0 + u) * BD] = fmaxf(val, 0.0f);
            }
        }
    }
}

// ---------------------------------------------------------------------------
// Launch
// inputs: 0=x (L,B,D), 1=damping (D,N,1), 2=decay (D,N,1),
//         3=ema (D,N,1), 4=proj (D,N), 5=residual_weight (D,)
// ---------------------------------------------------------------------------
extern "C" void kernel_launch(void* const* d_in, const int* in_sizes, int n_in,
                              void* d_out, int out_size) {
    const float* x       = (const float*)d_in[0];
    const float* damping = (const float*)d_in[1];
    const float* decay   = (const float*)d_in[2];
    const float* ema     = (const float*)d_in[3];
    const float* proj    = (const float*)d_in[4];
    const float* rw      = (const float*)d_in[5];
    float* out = (float*)d_out;

    coef_kernel<<<(D_SZ * N_HEADS + 255) / 256, 256>>>(damping, decay, ema, proj);

    dim3 sgrid(D_SZ / 128, B_SZ, NCHUNK);
    scan_local_kernel<<<sgrid, 256>>>(x);

    prefix_kernel<<<(BDN + 255) / 256, 256>>>();

    scan_out_kernel<<<sgrid, 256>>>(x, rw, out);
}